// round 5
// baseline (speedup 1.0000x reference)
#include <cuda_runtime.h>
#include <cuda_bf16.h>

// Batched Fast Walsh-Hadamard Transform, N = 4096 (12 butterfly stages),
// Sylvester ordering, scaled by 1/64. One CTA per row, single pass over HBM.
//
// Decomposition: H_4096 = H16 (bits 8-11)  x  H16 (bits 4-7)  x  H16 (bits 0-3)
// Each thread holds 16 floats; three in-register radix-16 phases with two
// shared-memory exchanges. XOR swizzle kills bank conflicts on the two
// conflict-prone patterns (verified by hand; middle phase is 2-way, benign).

#define FWHT_N   4096
#define THREADS  256
#define SWZ(e)   ((e) ^ (((e) >> 5) & 31))

__device__ __forceinline__ void h16(float v[16]) {
#pragma unroll
    for (int s = 1; s < 16; s <<= 1) {
#pragma unroll
        for (int i = 0; i < 16; i++) {
            if ((i & s) == 0) {
                float a = v[i];
                float b = v[i | s];
                v[i]     = a + b;
                v[i | s] = a - b;
            }
        }
    }
}

__global__ __launch_bounds__(THREADS) void fwht4096_kernel(
    const float* __restrict__ x, float* __restrict__ y)
{
    __shared__ float s[FWHT_N];

    const int t = threadIdx.x;
    const size_t base = (size_t)blockIdx.x * FWHT_N;

    float v[16];

    // ---- Phase 1: bits 8-11 in registers. e = t + 256*k ----
    // Global loads: 16 perfectly-coalesced LDG.32, front-batched (MLP=16).
#pragma unroll
    for (int k = 0; k < 16; k++)
        v[k] = x[base + (size_t)(t + (k << 8))];

    h16(v);

#pragma unroll
    for (int k = 0; k < 16; k++)
        s[SWZ(t + (k << 8))] = v[k];      // conflict-free under SWZ
    __syncthreads();

    // ---- Phase 2: bits 4-7 in registers. e = (t>>4)<<8 | k<<4 | (t&15) ----
    {
        const int e2 = ((t >> 4) << 8) | (t & 15);
#pragma unroll
        for (int k = 0; k < 16; k++)
            v[k] = s[SWZ(e2 + (k << 4))];  // 2-way conflict (benign)

        h16(v);

#pragma unroll
        for (int k = 0; k < 16; k++)
            s[SWZ(e2 + (k << 4))] = v[k];
    }
    __syncthreads();

    // ---- Phase 3: bits 0-3 in registers. e = 16*t + k ----
#pragma unroll
    for (int k = 0; k < 16; k++)
        v[k] = s[SWZ((t << 4) + k)];       // conflict-free under SWZ

    h16(v);

    // Scale by 1/sqrt(4096) and store as 4x STG.128 (full sector coverage).
    const float c = 1.0f / 64.0f;
    float4* yo = reinterpret_cast<float4*>(y + base + ((size_t)t << 4));
#pragma unroll
    for (int j = 0; j < 4; j++)
        yo[j] = make_float4(v[4 * j + 0] * c, v[4 * j + 1] * c,
                            v[4 * j + 2] * c, v[4 * j + 3] * c);
}

extern "C" void kernel_launch(void* const* d_in, const int* in_sizes, int n_in,
                              void* d_out, int out_size) {
    const float* x = (const float*)d_in[0];
    float* y = (float*)d_out;
    const int rows = in_sizes[0] / FWHT_N;   // 4 * 2048 = 8192
    fwht4096_kernel<<<rows, THREADS>>>(x, y);
}

// round 7
// speedup vs baseline: 1.2293x; 1.2293x over previous
#include <cuda_runtime.h>
#include <cuda_bf16.h>

// Batched FWHT, N = 4096, scaled by 1/64. One CTA per row, single HBM pass.
//
// Bit plan (12 bits, each transformed exactly once):
//   bits 0-3  : register index k        -> in-register h16
//   bits 4-8  : lane index              -> 5 __shfl_xor butterfly stages
//   bits 9-11 : warp index              -> ONE smem exchange, then h8 in regs
//
// Shared traffic is one 16KB store + one 16KB load per CTA (half of the
// two-exchange version), pulling l1tex off the roof so DRAM can bind.

#define FWHT_N   4096
#define THREADS  256
#define SWZ(e)   ((e) ^ (((e) >> 5) & 31))

__device__ __forceinline__ void bfly(float& a, float& b) {
    float t = a;
    a = t + b;
    b = t - b;
}

__global__ __launch_bounds__(THREADS) void fwht4096_kernel(
    const float* __restrict__ x, float* __restrict__ y)
{
    __shared__ float s[FWHT_N];

    const int t = threadIdx.x;
    const int lane = t & 31;
    const size_t base = (size_t)blockIdx.x * FWHT_N;

    float v[16];

    // ---- Load: e = 16*t + k  →  4x LDG.128, fully coalesced ----
    {
        const float4* xi = reinterpret_cast<const float4*>(x + base + ((size_t)t << 4));
#pragma unroll
        for (int q = 0; q < 4; q++) {
            float4 f = xi[q];
            v[4*q + 0] = f.x; v[4*q + 1] = f.y; v[4*q + 2] = f.z; v[4*q + 3] = f.w;
        }
    }

    // ---- bits 0-3: in-register H16 ----
#pragma unroll
    for (int st = 1; st < 16; st <<= 1)
#pragma unroll
        for (int i = 0; i < 16; i++)
            if ((i & st) == 0) bfly(v[i], v[i | st]);

    // ---- bits 4-8: lane-wise butterflies via shfl_xor ----
#pragma unroll
    for (int st = 1; st <= 16; st <<= 1) {
        const float sgn = (lane & st) ? -1.0f : 1.0f;
#pragma unroll
        for (int i = 0; i < 16; i++) {
            float p = __shfl_xor_sync(0xffffffffu, v[i], st);
            v[i] = fmaf(v[i], sgn, p);   // bit clear: v+p ; bit set: p-v
        }
    }

    // ---- smem exchange: bring warp bits 9-11 into register index ----
    // Store at word e = 16t + k. Under SWZ: even lanes -> banks k^m,
    // odd lanes -> 16 + (k^m): all 32 distinct, conflict-free.
#pragma unroll
    for (int k = 0; k < 16; k++)
        s[SWZ((t << 4) + k)] = v[k];
    __syncthreads();

    // Reload: e' = (j&7)<<9 | (j>>3)<<8 | t. Lane-consecutive -> conflict-free.
#pragma unroll
    for (int j = 0; j < 16; j++) {
        const int e2 = ((j & 7) << 9) | ((j >> 3) << 8) | t;
        v[j] = s[SWZ(e2)];
    }

    // ---- bits 9-11: H8 on register bits j0-j2, within each j3-half ----
#pragma unroll
    for (int st = 1; st <= 4; st <<= 1)
#pragma unroll
        for (int h = 0; h < 16; h += 8)
#pragma unroll
            for (int i = 0; i < 8; i++)
                if ((i & st) == 0) bfly(v[h + i], v[h + (i | st)]);

    // ---- Scale by 1/64 and store (coalesced per-j STG.32) ----
    const float c = 1.0f / 64.0f;
#pragma unroll
    for (int j = 0; j < 16; j++) {
        const int e2 = ((j & 7) << 9) | ((j >> 3) << 8) | t;
        y[base + e2] = v[j] * c;
    }
}

extern "C" void kernel_launch(void* const* d_in, const int* in_sizes, int n_in,
                              void* d_out, int out_size) {
    const float* x = (const float*)d_in[0];
    float* y = (float*)d_out;
    const int rows = in_sizes[0] / FWHT_N;   // 8192
    fwht4096_kernel<<<rows, THREADS>>>(x, y);
}

// round 9
// speedup vs baseline: 1.3239x; 1.0770x over previous
#include <cuda_runtime.h>
#include <cuda_bf16.h>

// Batched FWHT, N = 4096, scale 1/64. One CTA/row, single HBM pass, NO shuffles.
//
// Bit plan: three in-register H16 phases (pure FADD), two smem exchanges:
//   phase 1: e-bits 0-3  (register k, from LDG.128 layout e = 16t + k)
//   phase 2: e-bits 4-7  (register j, after exchange 1)
//   phase 3: e-bits 8-11 (register m, after exchange 2, permuted layout)
//
// Exchange 1: identity layout, swizzle S1 -> STS.128 conflict-free, LDS.32
//             conflict-free (all 5 lane bits land in bank index).
// Exchange 2: layout g2 = tHi | tLo<<4 | j<<8, swizzle S2 -> STS.32 2-way
//             (provably minimal), LDS.128 conflict-free.

#define FWHT_N  4096
#define THREADS 256

// Swizzles operate on 16B-unit index u (= word>>2); they XOR only u-bits 0-2,
// i.e. word-bits 2-4, so 128-bit accesses stay 16B-contiguous.
#define S1(u) ((u) ^ (((u) >> 3) & 3) ^ ((((u) >> 6) & 1) << 2))
#define S2(u) ((u) ^ (((u) >> 3) & 7) ^ (((u) >> 6) & 7))

__device__ __forceinline__ void h16(float v[16]) {
#pragma unroll
    for (int st = 1; st < 16; st <<= 1)
#pragma unroll
        for (int i = 0; i < 16; i++)
            if ((i & st) == 0) {
                float a = v[i], b = v[i | st];
                v[i]      = a + b;
                v[i | st] = a - b;
            }
}

__global__ __launch_bounds__(THREADS) void fwht4096_kernel(
    const float* __restrict__ x, float* __restrict__ y)
{
    __shared__ float s[FWHT_N];
    float4* s4 = reinterpret_cast<float4*>(s);

    const int t    = threadIdx.x;
    const int tLo  = t & 15;          // e-bits 0-3 (thread part)
    const int tHi  = t >> 4;          // e-bits 8-11 (thread part)
    const size_t base = (size_t)blockIdx.x * FWHT_N;

    float v[16];

    // ---- Load: e = 16t + k  ->  4x LDG.128 ----
    {
        const float4* xi = reinterpret_cast<const float4*>(x + base + ((size_t)t << 4));
#pragma unroll
        for (int q = 0; q < 4; q++) {
            float4 f = xi[q];
            v[4*q+0] = f.x; v[4*q+1] = f.y; v[4*q+2] = f.z; v[4*q+3] = f.w;
        }
    }

    // ---- Phase 1: H16 on e-bits 0-3 ----
    h16(v);

    // ---- Exchange 1 store: identity layout, STS.128 x4 (conflict-free) ----
    {
        const int ub = t << 2;                       // u = 4t + q
#pragma unroll
        for (int q = 0; q < 4; q++) {
            const int u = ub + q;
            s4[S1(u)] = make_float4(v[4*q+0], v[4*q+1], v[4*q+2], v[4*q+3]);
        }
    }
    __syncthreads();

    // ---- Exchange 1 reload: e' = tHi<<8 | j<<4 | tLo, LDS.32 x16 (CF) ----
    {
        const int ubase = (tHi << 6) | (tLo >> 2);   // u' without j
        const int w0    = tLo & 3;                   // word within 16B unit
#pragma unroll
        for (int j = 0; j < 16; j++) {
            const int u = ubase + (j << 2);
            v[j] = s[(S1(u) << 2) | w0];
        }
    }

    // ---- Phase 2: H16 on e-bits 4-7 ----
    h16(v);
    __syncthreads();

    // ---- Exchange 2 store: g2 = tHi | tLo<<4 | j<<8, STS.32 x16 (2-way) ----
    {
        const int gbase = tHi | (tLo << 4);
#pragma unroll
        for (int j = 0; j < 16; j++) {
            const int g = gbase + (j << 8);
            const int u = g >> 2;
            s[(S2(u) << 2) | (g & 3)] = v[j];
        }
    }
    __syncthreads();

    // ---- Exchange 2 reload: e'' = m<<8 | t, LDS.128 x4 (conflict-free) ----
    {
        const int gb = ((t & 15) << 4) | ((t >> 4) << 8);  // g2 without m
        const int ub = gb >> 2;                            // low 2 bits of gb are 0
#pragma unroll
        for (int q = 0; q < 4; q++) {
            float4 f = s4[S2(ub + q)];
            v[4*q+0] = f.x; v[4*q+1] = f.y; v[4*q+2] = f.z; v[4*q+3] = f.w;
        }
    }

    // ---- Phase 3: H16 on e-bits 8-11 ----
    h16(v);

    // ---- Store: e = m<<8 | t, coalesced STG.32 x16, scale 1/64 ----
    const float c = 1.0f / 64.0f;
#pragma unroll
    for (int m = 0; m < 16; m++)
        y[base + (m << 8) + t] = v[m] * c;
}

extern "C" void kernel_launch(void* const* d_in, const int* in_sizes, int n_in,
                              void* d_out, int out_size) {
    const float* x = (const float*)d_in[0];
    float* y = (float*)d_out;
    const int rows = in_sizes[0] / FWHT_N;   // 8192
    fwht4096_kernel<<<rows, THREADS>>>(x, y);
}

// round 10
// speedup vs baseline: 1.3342x; 1.0078x over previous
#include <cuda_runtime.h>
#include <cuda_bf16.h>

// Batched FWHT, N = 4096, scale 1/64. One CTA/row, single HBM pass.
//
// Wavefront-minimal plan (L1 line/bank wavefronts per CTA, 8 warps):
//   load : e = t | k<<8        LDG.32 x16, lane-coalesced      -> 128 wf
//   ex1  : w1 = e ^ ((e>>4)&31)      STS/LDS.32 conflict-free  -> 256 wf
//   ex2  : w2 = e ^ ((e>>5)&15) ^ (e8<<4)  STS/LDS.32 CF       -> 256 wf
//   store: e = (t&15) | r<<4 | (t>>4)<<8  two 64B runs/instr   -> 256 wf
// Phases (in-register H16, pure FADD): P1 e[8:12], P2 e[0:4], P3 e[4:8].

#define FWHT_N  4096
#define THREADS 256

__device__ __forceinline__ int swz1(int e) {
    return e ^ ((e >> 4) & 31);
}
__device__ __forceinline__ int swz2(int e) {
    return e ^ ((e >> 5) & 15) ^ (((e >> 8) & 1) << 4);
}

__device__ __forceinline__ void h16(float v[16]) {
#pragma unroll
    for (int st = 1; st < 16; st <<= 1)
#pragma unroll
        for (int i = 0; i < 16; i++)
            if ((i & st) == 0) {
                float a = v[i], b = v[i | st];
                v[i]      = a + b;
                v[i | st] = a - b;
            }
}

__global__ __launch_bounds__(THREADS) void fwht4096_kernel(
    const float* __restrict__ x, float* __restrict__ y)
{
    __shared__ float s[FWHT_N];

    const int t = threadIdx.x;
    const size_t base = (size_t)blockIdx.x * FWHT_N;

    float v[16];

    // ---- Load: e = t | k<<8, reg k = e[8:12]. Coalesced LDG.32 x16. ----
    {
        const float* xr = x + base + t;
#pragma unroll
        for (int k = 0; k < 16; k++)
            v[k] = xr[k << 8];
    }

    // ---- P1: H16 on e[8:12] ----
    h16(v);

    // ---- Exchange 1: identity e, swizzle w1. Store CF, load CF. ----
#pragma unroll
    for (int k = 0; k < 16; k++)
        s[swz1(t | (k << 8))] = v[k];
    __syncthreads();

    // L1: thread holds e[4:12] = t, reg j = e[0:4]: e = j | t<<4
#pragma unroll
    for (int j = 0; j < 16; j++)
        v[j] = s[swz1(j | (t << 4))];

    // ---- P2: H16 on e[0:4] ----
    h16(v);
    __syncthreads();

    // ---- Exchange 2: swizzle w2. Store CF, load CF. ----
#pragma unroll
    for (int j = 0; j < 16; j++)
        s[swz2(j | (t << 4))] = v[j];
    __syncthreads();

    // L2: thread holds e[0:4] = t&15, e[8:12] = t>>4; reg r = e[4:8]
    {
        const int e0 = (t & 15) | ((t >> 4) << 8);
#pragma unroll
        for (int r = 0; r < 16; r++)
            v[r] = s[swz2(e0 | (r << 4))];
    }

    // ---- P3: H16 on e[4:8] ----
    h16(v);

    // ---- Store: e = (t&15) | r<<4 | (t>>4)<<8, scale 1/64. ----
    // Per instr: lanes 0-15 and 16-31 each write one full 64B run (2 wf).
    {
        const float c = 1.0f / 64.0f;
        float* yr = y + base + (t & 15) + ((t >> 4) << 8);
#pragma unroll
        for (int r = 0; r < 16; r++)
            yr[r << 4] = v[r] * c;
    }
}

extern "C" void kernel_launch(void* const* d_in, const int* in_sizes, int n_in,
                              void* d_out, int out_size) {
    const float* x = (const float*)d_in[0];
    float* y = (float*)d_out;
    const int rows = in_sizes[0] / FWHT_N;   // 8192
    fwht4096_kernel<<<rows, THREADS>>>(x, y);
}